// round 14
// baseline (speedup 1.0000x reference)
#include <cuda_runtime.h>
#include <cstdint>

// depthconv1d: B=8, L=16384, C=512, K=31, SAME padding, fp32 NWC.
// out[b,w,c] = sum_k x[b, w+k-15, c] * ker[k*C + c] + bias[c]
//
// R14: warp-specialized producer/consumer. 11 prior variants show any
// structure where FMA warps also issue/await loads equilibrates at
// ~4.5-5.1 TB/s. Here 4 producer warps do nothing but cp.async whole
// 31KB stages (ring of 4, mbarrier handoff) while 8 consumer warps do
// nothing but FMA2 from smem. Load issue is decoupled from compute by
// construction: if HBM is the real wall, consumers block on 'full' and
// DRAM runs continuously.

#define B_ 8
#define L_ 16384
#define C_ 512
#define K_ 31
#define HALF_ 15
#define T_ 8                     // outputs per consumer thread
#define CB_ 128                  // channels per CTA
#define WB_ 32                   // output rows per stage
#define NSTAGE_ 4
#define NITER_ 16                // stages walked per CTA
#define NR_ (WB_ + K_ - 1)       // 62 staged rows per stage
#define ROWB_ (CB_ * 4)          // 512 B per staged row
#define BUFB_ (NR_ * ROWB_)      // 31744 B per stage
#define WSB_ (K_ * ROWB_)        // 15872 B weights
#define WS_OFF_ (NSTAGE_ * BUFB_)          // 126976
#define MBAR_OFF_ (WS_OFF_ + WSB_)         // 142848
#define SMEM_TOTAL_ (MBAR_OFF_ + 64)       // 142912 -> 1 CTA/SM
#define XW_ 10                   // register x-ring slots
#define NP_ (T_ + K_ - 1)        // 38 rows read per consumer thread

using u64 = unsigned long long;

__device__ __forceinline__ u64 fma2(u64 a, u64 b, u64 c) {
    u64 d;
    asm("fma.rn.f32x2 %0, %1, %2, %3;" : "=l"(d) : "l"(a), "l"(b), "l"(c));
    return d;
}
__device__ __forceinline__ u64 add2(u64 a, u64 b) {
    u64 d;
    asm("add.rn.f32x2 %0, %1, %2;" : "=l"(d) : "l"(a), "l"(b));
    return d;
}
__device__ __forceinline__ void cp_async16(uint32_t sa, const void* g) {
    asm volatile("cp.async.cg.shared.global [%0], [%1], 16;"
                 :: "r"(sa), "l"(g) : "memory");
}
#define CP_COMMIT()    asm volatile("cp.async.commit_group;" ::: "memory")
#define CP_WAIT_ALL()  asm volatile("cp.async.wait_group 0;" ::: "memory")

__device__ __forceinline__ void mbar_init(uint32_t a, uint32_t cnt) {
    asm volatile("mbarrier.init.shared.b64 [%0], %1;"
                 :: "r"(a), "r"(cnt) : "memory");
}
__device__ __forceinline__ void mbar_arrive(uint32_t a) {
    asm volatile("mbarrier.arrive.shared.b64 _, [%0];"
                 :: "r"(a) : "memory");
}
__device__ __forceinline__ void mbar_wait(uint32_t a, uint32_t ph) {
    asm volatile(
        "{\n\t"
        ".reg .pred P;\n\t"
        "W_%=:\n\t"
        "mbarrier.try_wait.parity.acquire.cta.shared::cta.b64 P, [%0], %1, 0x989680;\n\t"
        "@!P bra W_%=;\n\t"
        "}"
        :: "r"(a), "r"(ph) : "memory");
}

template <bool EDGE>
__device__ __forceinline__ void run_body(
    const float* __restrict__ x, const float* __restrict__ w,
    const float* __restrict__ bias, float* __restrict__ out, char* smem)
{
    char* ws = smem + WS_OFF_;
    const int tid  = threadIdx.x;
    const int wid  = tid >> 5;
    const int lane = tid & 31;
    const int cb0  = blockIdx.y * CB_;
    const int b    = blockIdx.z;
    const int W0   = blockIdx.x * (WB_ * NITER_);

    uint32_t sa0 = (uint32_t)__cvta_generic_to_shared(smem);
    uint32_t wsa = sa0 + WS_OFF_;
    uint32_t mba = sa0 + MBAR_OFF_;       // full[s]=mba+8s, empty[s]=mba+32+8s

    // ---- Init barriers + stage weights (all 384 threads) ----
    if (tid == 0) {
#pragma unroll
        for (int s = 0; s < NSTAGE_; s++) {
            mbar_init(mba + s * 8, 1);        // full: 1 producer arrival
            mbar_init(mba + 32 + s * 8, 8);   // empty: 8 consumer warps
        }
    }
#pragma unroll
    for (int r = 0; r < 3; r++) {
        int chunk = r * 384 + tid;
        if (chunk < K_ * 32) {
            int k = chunk >> 5, c = chunk & 31;
            cp_async16(wsa + k * ROWB_ + c * 16,
                       reinterpret_cast<const char*>(w)
                       + ((long long)k * C_ + cb0) * 4ll + c * 16);
        }
    }
    CP_COMMIT();
    CP_WAIT_ALL();
    __syncthreads();   // barriers initialized + weights visible

    if (wid >= 8) {
        // ================= PRODUCER (wid 8..11) =================
        const int p = wid - 8;                 // owns stage p
        char* dst = smem + p * BUFB_;
        uint32_t dsta = sa0 + p * BUFB_;
        const char* gx = reinterpret_cast<const char*>(x)
                       + ((long long)b * L_ * C_ + cb0) * 4ll;
        uint32_t ph = 1;                       // first empty-wait passes
#pragma unroll 1
        for (int i = p; i < NITER_; i += NSTAGE_) {
            mbar_wait(mba + 32 + p * 8, ph);   // stage p free?
            ph ^= 1;
            int row0 = W0 - HALF_ + i * WB_;
#pragma unroll 1
            for (int r = 0; r < NR_; r++) {
                int wg = row0 + r;
                if (!EDGE || ((unsigned)wg < (unsigned)L_)) {
                    cp_async16(dsta + r * ROWB_ + lane * 16,
                               gx + (long long)wg * (C_ * 4) + lane * 16);
                } else {
                    *reinterpret_cast<uint4*>(dst + r * ROWB_ + lane * 16)
                        = make_uint4(0u, 0u, 0u, 0u);
                }
            }
            CP_COMMIT();
            CP_WAIT_ALL();                     // this lane's data landed
            __syncwarp();                      // whole stage landed
            if (lane == 0) mbar_arrive(mba + p * 8);   // full[p]
        }
    } else {
        // ================= CONSUMER (wid 0..7) =================
        const int pair = tid & 63;             // channels cb0 + 2*pair
        const int grp  = tid >> 6;             // w-subgroup 0..3 (T=8 rows)
        const char* wsp = ws + pair * 8;
        const u64 bv = *reinterpret_cast<const u64*>(bias + cb0 + pair * 2);
        char* obB = reinterpret_cast<char*>(out)
                  + ((long long)((long long)b * L_ + W0 + grp * T_) * C_
                     + cb0 + pair * 2) * 4ll;
        uint32_t ph = 0;
#pragma unroll 1
        for (int i = 0; i < NITER_; i++) {
            int s = i & (NSTAGE_ - 1);
            mbar_wait(mba + s * 8, ph);        // stage s full?
            if (s == NSTAGE_ - 1) ph ^= 1;

            const char* xsp = smem + s * BUFB_ + (grp * T_) * ROWB_ + pair * 8;

            u64 xv[XW_];
#pragma unroll
            for (int q = 0; q < XW_; q++)
                xv[q] = *reinterpret_cast<const u64*>(xsp + q * ROWB_);

            u64 acc[T_];
#pragma unroll
            for (int t = 0; t < T_; t++) acc[t] = 0ull;

            u64 wcur = *reinterpret_cast<const u64*>(wsp);
#pragma unroll
            for (int k = 0; k < K_; k++) {
                u64 wnext = 0ull;
                if (k + 1 < K_)
                    wnext = *reinterpret_cast<const u64*>(wsp + (k + 1) * ROWB_);
#pragma unroll
                for (int t = 0; t < T_; t++)
                    acc[t] = fma2(xv[(k + t) % XW_], wcur, acc[t]);
                if (k + XW_ < NP_)
                    xv[(k + XW_) % XW_] =
                        *reinterpret_cast<const u64*>(xsp + (k + XW_) * ROWB_);
                wcur = wnext;
            }

            char* ob = obB + (long long)i * WB_ * (C_ * 4);
#pragma unroll
            for (int t = 0; t < T_; t++)
                *reinterpret_cast<u64*>(ob + (long long)t * (C_ * 4))
                    = add2(acc[t], bv);

            __syncwarp();                      // all lanes done with stage s
            if (lane == 0) mbar_arrive(mba + 32 + s * 8);   // empty[s]
        }
    }
}

__global__ __launch_bounds__(384, 1)
void depthconv1d_kernel(const float* __restrict__ x,
                        const float* __restrict__ w,
                        const float* __restrict__ bias,
                        float* __restrict__ out)
{
    extern __shared__ char smem[];
    if (blockIdx.x == 0 || blockIdx.x == gridDim.x - 1)
        run_body<true>(x, w, bias, out, smem);
    else
        run_body<false>(x, w, bias, out, smem);
}

extern "C" void kernel_launch(void* const* d_in, const int* in_sizes, int n_in,
                              void* d_out, int out_size)
{
    const float* x    = (const float*)d_in[0];  // [8, 16384, 512]
    const float* ker  = (const float*)d_in[1];  // [31, 512, 1]
    const float* bias = (const float*)d_in[2];  // [512]
    float* out = (float*)d_out;                 // [8, 16384, 512]

    cudaFuncSetAttribute(depthconv1d_kernel,
                         cudaFuncAttributeMaxDynamicSharedMemorySize,
                         SMEM_TOTAL_);

    dim3 grid(L_ / (WB_ * NITER_), C_ / CB_, B_);   // (32, 4, 8) = 1024
    dim3 block(384);
    depthconv1d_kernel<<<grid, block, SMEM_TOTAL_>>>(x, ker, bias, out);
}

// round 15
// speedup vs baseline: 1.4332x; 1.4332x over previous
#include <cuda_runtime.h>
#include <cstdint>

// depthconv1d: B=8, L=16384, C=512, K=31, SAME padding, fp32 NWC.
// out[b,w,c] = sum_k x[b, w+k-15, c] * ker[k*C + c] + bias[c]
//
// R15 = R4 champion (one-shot cp.async stage + k-outer register-ring
// compute) with the tile doubled to WB=64. Rationale: all pipeline /
// specialization variants (R6,R12,R13,R14) regressed; R4-style one-shot
// CTAs hold the BW record. Remaining slack is per-CTA fixed cost: WB=32
// moves 47.6KB (x halo 1.94x + 15.9KB weights) per 16KB of output. WB=64
// cuts halo to 1.47x, halves weight staging and CTA count, keeping the
// proven structure. 62.5KB dynamic smem -> 3 CTAs/SM, regs capped at 85.

#define B_ 8
#define L_ 16384
#define C_ 512
#define K_ 31
#define HALF_ 15
#define T_ 16        // outputs per thread
#define WB_ 64       // w positions per block (4 grps x T)
#define CB_ 128      // channels per block
#define NR_ (WB_ + K_ - 1)   // 94 input rows staged
#define ROWB_ (CB_ * 4)      // 512 B per staged row
#define XBYTES_ (NR_ * ROWB_)          // 48128
#define WSB_ (K_ * ROWB_)              // 15872
#define SMEM_TOTAL_ (XBYTES_ + WSB_)   // 64000 B -> 3 CTAs/SM
#define XW_ 18       // register x-ring slots
#define NP_ (T_ + K_ - 1)    // 46 rows read per thread

using u64 = unsigned long long;

__device__ __forceinline__ u64 fma2(u64 a, u64 b, u64 c) {
    u64 d;
    asm("fma.rn.f32x2 %0, %1, %2, %3;" : "=l"(d) : "l"(a), "l"(b), "l"(c));
    return d;
}
__device__ __forceinline__ u64 add2(u64 a, u64 b) {
    u64 d;
    asm("add.rn.f32x2 %0, %1, %2;" : "=l"(d) : "l"(a), "l"(b));
    return d;
}
__device__ __forceinline__ void cp_async16(uint32_t sa, const void* g) {
    asm volatile("cp.async.cg.shared.global [%0], [%1], 16;"
                 :: "r"(sa), "l"(g) : "memory");
}
__device__ __forceinline__ void cp_async_wait_all() {
    asm volatile("cp.async.commit_group;\n\tcp.async.wait_group 0;" ::: "memory");
}

template <bool EDGE>
__device__ __forceinline__ void run_body(
    const float* __restrict__ x, const float* __restrict__ w,
    const float* __restrict__ bias, float* __restrict__ out, char* smem)
{
    char* xs = smem;
    char* ws = smem + XBYTES_;
    const int tid = threadIdx.x;
    const int w0  = blockIdx.x * WB_;
    const int cb0 = blockIdx.y * CB_;
    const int b   = blockIdx.z;

    uint32_t sa0 = (uint32_t)__cvta_generic_to_shared(xs);
    uint32_t wsa = sa0 + XBYTES_;

    // ---- Stage x tile: 94 rows x 512B = 3008 16B chunks over 256 thr ----
    {
        const char* gx = reinterpret_cast<const char*>(x)
                       + ((long long)b * L_ * C_ + cb0) * 4ll;
#pragma unroll
        for (int j = 0; j < 12; j++) {
            int chunk = j * 256 + tid;
            if (chunk < NR_ * 32) {
                int r = chunk >> 5, lane = chunk & 31;
                int wg = w0 - HALF_ + r;
                if (!EDGE || ((unsigned)wg < (unsigned)L_)) {
                    cp_async16(sa0 + r * ROWB_ + lane * 16,
                               gx + (long long)wg * (C_ * 4) + lane * 16);
                } else {
                    *reinterpret_cast<uint4*>(xs + r * ROWB_ + lane * 16)
                        = make_uint4(0u, 0u, 0u, 0u);
                }
            }
        }
    }

    // ---- Stage weights: 31 rows x 512B = 992 chunks over 256 thr ----
    {
        const char* gw = reinterpret_cast<const char*>(w) + cb0 * 4;
#pragma unroll
        for (int j = 0; j < 4; j++) {
            int chunk = j * 256 + tid;
            if (chunk < K_ * 32) {
                int k = chunk >> 5, lane = chunk & 31;
                cp_async16(wsa + k * ROWB_ + lane * 16,
                           gw + (long long)k * (C_ * 4) + lane * 16);
            }
        }
    }

    cp_async_wait_all();
    __syncthreads();

    // ---- Compute: thread = channel pair x 16 outputs, k-outer, x-ring ----
    const int pair = tid & 63;              // channels cb0 + 2*pair
    const int grp  = tid >> 6;              // w-subgroup 0..3
    const char* xsp = xs + (grp * T_) * ROWB_ + pair * 8;
    const char* wsp = ws + pair * 8;

    u64 xv[XW_];
#pragma unroll
    for (int p = 0; p < XW_; p++)
        xv[p] = *reinterpret_cast<const u64*>(xsp + p * ROWB_);

    u64 acc[T_];
#pragma unroll
    for (int t = 0; t < T_; t++) acc[t] = 0ull;

    u64 wcur = *reinterpret_cast<const u64*>(wsp);
#pragma unroll
    for (int k = 0; k < K_; k++) {
        u64 wnext = 0ull;
        if (k + 1 < K_)
            wnext = *reinterpret_cast<const u64*>(wsp + (k + 1) * ROWB_);
#pragma unroll
        for (int t = 0; t < T_; t++)
            acc[t] = fma2(xv[(k + t) % XW_], wcur, acc[t]);
        if (k + XW_ < NP_)
            xv[(k + XW_) % XW_] =
                *reinterpret_cast<const u64*>(xsp + (k + XW_) * ROWB_);
        wcur = wnext;
    }

    u64 bv = *reinterpret_cast<const u64*>(bias + cb0 + pair * 2);
    char* ob = reinterpret_cast<char*>(out)
             + ((long long)((long long)b * L_ + w0 + grp * T_) * C_
                + cb0 + pair * 2) * 4ll;
#pragma unroll
    for (int t = 0; t < T_; t++)
        *reinterpret_cast<u64*>(ob + (long long)t * (C_ * 4)) = add2(acc[t], bv);
}

__global__ __launch_bounds__(256, 3)
void depthconv1d_kernel(const float* __restrict__ x,
                        const float* __restrict__ w,
                        const float* __restrict__ bias,
                        float* __restrict__ out)
{
    extern __shared__ char smem[];
    if (blockIdx.x == 0 || blockIdx.x == gridDim.x - 1)
        run_body<true>(x, w, bias, out, smem);
    else
        run_body<false>(x, w, bias, out, smem);
}

extern "C" void kernel_launch(void* const* d_in, const int* in_sizes, int n_in,
                              void* d_out, int out_size)
{
    const float* x    = (const float*)d_in[0];  // [8, 16384, 512]
    const float* ker  = (const float*)d_in[1];  // [31, 512, 1]
    const float* bias = (const float*)d_in[2];  // [512]
    float* out = (float*)d_out;                 // [8, 16384, 512]

    cudaFuncSetAttribute(depthconv1d_kernel,
                         cudaFuncAttributeMaxDynamicSharedMemorySize,
                         SMEM_TOTAL_);

    dim3 grid(L_ / WB_, C_ / CB_, B_);   // (256, 4, 8) = 8192 blocks
    dim3 block(256);
    depthconv1d_kernel<<<grid, block, SMEM_TOTAL_>>>(x, ker, bias, out);
}